// round 7
// baseline (speedup 1.0000x reference)
#include <cuda_runtime.h>
#include <cuda_bf16.h>
#include <cstdint>
#include <math.h>

#define Hdim   1024
#define RANKK  4
#define BATCHN 128
#define TSTEPS 256
#define MTOT   (BATCHN * TSTEPS)      // 32768

// ======================= helpers =======================
__device__ __forceinline__ uint32_t smem_u32(const void* p) {
    uint32_t a;
    asm("{ .reg .u64 t; cvta.to.shared.u64 t, %1; cvt.u32.u64 %0, t; }" : "=r"(a) : "l"(p));
    return a;
}
__device__ __forceinline__ void cp16(uint32_t dst, const void* src) {
    asm volatile("cp.async.cg.shared.global [%0], [%1], 16;" :: "r"(dst), "l"(src) : "memory");
}
#define CP_COMMIT() asm volatile("cp.async.commit_group;" ::: "memory")

__device__ __forceinline__ void ldsm4(uint32_t* r, uint32_t addr) {
    asm volatile("ldmatrix.sync.aligned.m8n8.x4.shared.b16 {%0,%1,%2,%3}, [%4];"
        : "=r"(r[0]), "=r"(r[1]), "=r"(r[2]), "=r"(r[3]) : "r"(addr));
}
__device__ __forceinline__ void ldsm4t(uint32_t* r, uint32_t addr) {
    asm volatile("ldmatrix.sync.aligned.m8n8.x4.trans.shared.b16 {%0,%1,%2,%3}, [%4];"
        : "=r"(r[0]), "=r"(r[1]), "=r"(r[2]), "=r"(r[3]) : "r"(addr));
}
__device__ __forceinline__ void mma16816(float* c, const uint32_t* a, uint32_t b0, uint32_t b1) {
    asm volatile("mma.sync.aligned.m16n8k16.row.col.f32.bf16.bf16.f32 "
        "{%0,%1,%2,%3}, {%4,%5,%6,%7}, {%8,%9}, {%0,%1,%2,%3};"
        : "+f"(c[0]), "+f"(c[1]), "+f"(c[2]), "+f"(c[3])
        : "r"(a[0]), "r"(a[1]), "r"(a[2]), "r"(a[3]), "r"(b0), "r"(b1));
}

// ======================= bf16 split scratch =======================
__device__ __align__(256) __nv_bfloat16 g_xh[(size_t)MTOT * Hdim];   // 64 MB
__device__ __align__(256) __nv_bfloat16 g_xl[(size_t)MTOT * Hdim];   // 64 MB
__device__ __align__(256) __nv_bfloat16 g_Bh[(size_t)Hdim * Hdim];   // 2 MB  [k][n]
__device__ __align__(256) __nv_bfloat16 g_Bl[(size_t)Hdim * Hdim];

__global__ __launch_bounds__(256) void split_x_kernel(const float* __restrict__ x) {
    size_t i = (size_t)blockIdx.x * 256 + threadIdx.x;
    float4 v = ((const float4*)x)[i];
    union { __nv_bfloat16 b[4]; uint2 u; } Hh, Ll;
    Hh.b[0] = __float2bfloat16(v.x); Ll.b[0] = __float2bfloat16(v.x - __bfloat162float(Hh.b[0]));
    Hh.b[1] = __float2bfloat16(v.y); Ll.b[1] = __float2bfloat16(v.y - __bfloat162float(Hh.b[1]));
    Hh.b[2] = __float2bfloat16(v.z); Ll.b[2] = __float2bfloat16(v.z - __bfloat162float(Hh.b[2]));
    Hh.b[3] = __float2bfloat16(v.w); Ll.b[3] = __float2bfloat16(v.w - __bfloat162float(Hh.b[3]));
    *(uint2*)&g_xh[4 * i] = Hh.u;
    *(uint2*)&g_xl[4 * i] = Ll.u;
}

__global__ __launch_bounds__(256) void split_B_kernel(const float* __restrict__ B) {
    size_t i = (size_t)blockIdx.x * 256 + threadIdx.x;
    float4 v = ((const float4*)B)[i];
    union { __nv_bfloat16 b[4]; uint2 u; } Hh, Ll;
    Hh.b[0] = __float2bfloat16(v.x); Ll.b[0] = __float2bfloat16(v.x - __bfloat162float(Hh.b[0]));
    Hh.b[1] = __float2bfloat16(v.y); Ll.b[1] = __float2bfloat16(v.y - __bfloat162float(Hh.b[1]));
    Hh.b[2] = __float2bfloat16(v.z); Ll.b[2] = __float2bfloat16(v.z - __bfloat162float(Hh.b[2]));
    Hh.b[3] = __float2bfloat16(v.w); Ll.b[3] = __float2bfloat16(v.w - __bfloat162float(Hh.b[3]));
    *(uint2*)&g_Bh[4 * i] = Hh.u;
    *(uint2*)&g_Bl[4 * i] = Ll.u;
}

// ======================= HMMA GEMM v2 =======================
// C[32768,1024] = xh@Bh + xh@Bl + xl@Bh (virtual K = 3*1024, chunks of 32)
// Tile 128(M) x 256(N) x 32(K), 256 threads, 8 warps (4M x 2N), warp tile 32x128.
// 4-stage cp.async pipeline, 1 CTA/SM.
#define BK      32
#define NCHNK   96                    // 3 slabs * 32 chunks
#define ASTRB   80                    // bytes per A smem row (40 halves)
#define BSTRB   528                   // bytes per B smem row (264 halves)
#define ASTG    (128 * ASTRB)         // 10240 B
#define BSTG    (BK * BSTRB)          // 16896 B
#define STG     (ASTG + BSTG)         // 27136 B
#define NSTAGE  4
#define SMEM_GEMM (NSTAGE * STG)      // 108544 B

__device__ __forceinline__ void load_chunk_g(uint32_t sA, uint32_t sB,
                                             const __nv_bfloat16* __restrict__ gA,
                                             const __nv_bfloat16* __restrict__ gB,
                                             int m0, int n0, int k0, int tid) {
    #pragma unroll
    for (int i = 0; i < 2; i++) {               // A: 128 rows x 4 segs = 512 cp16
        int o = tid + i * 256;
        int row = o >> 2, seg = o & 3;
        cp16(sA + row * ASTRB + seg * 16, gA + (size_t)(m0 + row) * Hdim + k0 + seg * 8);
    }
    #pragma unroll
    for (int i = 0; i < 4; i++) {               // B: 32 rows x 32 segs = 1024 cp16
        int o = tid + i * 256;
        int row = o >> 5, seg = o & 31;
        cp16(sB + row * BSTRB + seg * 16, gB + (size_t)(k0 + row) * Hdim + n0 + seg * 8);
    }
}

__global__ __launch_bounds__(256, 1) void gemm_mma(float* __restrict__ C) {
    extern __shared__ char smem[];
    const uint32_t sb = smem_u32(smem);
    const int tid = threadIdx.x, lane = tid & 31, wid = tid >> 5;
    const int wm = (wid >> 1) * 32;      // 4 warp rows
    const int wn = (wid & 1) * 128;      // 2 warp cols
    const int n0 = blockIdx.x * 256;
    const int m0 = blockIdx.y * 128;

    const __nv_bfloat16* slabA[3] = { g_xh, g_xh, g_xl };
    const __nv_bfloat16* slabB[3] = { g_Bh, g_Bl, g_Bh };

    const int r8 = lane & 7, g = lane >> 3;
    const int mrow = (g & 1) * 8 + r8;
    const int kcolB = (g >> 1) * 16;
    const uint32_t offA0 = (uint32_t)(wm + mrow) * ASTRB + kcolB;
    const uint32_t offA1 = (uint32_t)(wm + 16 + mrow) * ASTRB + kcolB;
    uint32_t offB[8];
    #pragma unroll
    for (int ng = 0; ng < 8; ng++)
        offB[ng] = (uint32_t)mrow * BSTRB + (uint32_t)(wn + ng * 16) * 2 + kcolB;

    float acc[2][16][4] = {};

    // prologue: chunks 0..2
    #pragma unroll
    for (int p = 0; p < NSTAGE - 1; p++) {
        load_chunk_g(sb + p * STG, sb + p * STG + ASTG, slabA[0], slabB[0], m0, n0, p * BK, tid);
        CP_COMMIT();
    }

    for (int c = 0; c < NCHNK; c++) {
        const int s = c & (NSTAGE - 1);
        asm volatile("cp.async.wait_group 2;" ::: "memory");
        __syncthreads();

        if (c + NSTAGE - 1 < NCHNK) {
            const int cn = c + NSTAGE - 1, sn = cn & (NSTAGE - 1);
            load_chunk_g(sb + sn * STG, sb + sn * STG + ASTG,
                         slabA[cn >> 5], slabB[cn >> 5], m0, n0, (cn & 31) * BK, tid);
        }
        CP_COMMIT();   // uniform one group per iteration

        const uint32_t aB = sb + s * STG;
        const uint32_t bB = aB + ASTG;
        #pragma unroll
        for (int ks = 0; ks < 2; ks++) {
            uint32_t a[2][4];
            ldsm4(a[0], aB + offA0 + ks * 32);
            ldsm4(a[1], aB + offA1 + ks * 32);
            uint32_t b[8][4];
            #pragma unroll
            for (int ng = 0; ng < 8; ng++)
                ldsm4t(b[ng], bB + offB[ng] + ks * 16 * BSTRB);
            #pragma unroll
            for (int mt = 0; mt < 2; mt++)
                #pragma unroll
                for (int nt = 0; nt < 16; nt++)
                    mma16816(acc[mt][nt], a[mt], b[nt >> 1][(nt & 1) * 2], b[nt >> 1][(nt & 1) * 2 + 1]);
        }
    }

    // epilogue
    #pragma unroll
    for (int mt = 0; mt < 2; mt++) {
        const int row = m0 + wm + mt * 16 + (lane >> 2);
        #pragma unroll
        for (int nt = 0; nt < 16; nt++) {
            const int col = n0 + wn + nt * 8 + (lane & 3) * 2;
            *(float2*)&C[(size_t)row * Hdim + col]       = make_float2(acc[mt][nt][0], acc[mt][nt][1]);
            *(float2*)&C[(size_t)(row + 8) * Hdim + col] = make_float2(acc[mt][nt][2], acc[mt][nt][3]);
        }
    }
}

// ======================= recurrence v2: 128 threads x 8 elems =======================
__device__ __forceinline__ float tanh_fast(float x) {
    float ax = fabsf(x);
    float e  = __expf(-2.0f * ax);
    float r  = (1.0f - e) * __frcp_rn(1.0f + e);
    return copysignf(r, x);
}
__device__ __forceinline__ float dot4(float4 a, float4 b) {
    return fmaf(a.x, b.x, fmaf(a.y, b.y, fmaf(a.z, b.z, a.w * b.w)));
}

__global__ __launch_bounds__(128) void recur(const float* __restrict__ h0,
                                             const float* __restrict__ dvec,
                                             const float* __restrict__ L,
                                             const float* __restrict__ R,
                                             float* __restrict__ out) {
    const int b = blockIdx.x, tid = threadIdx.x;
    const int warp = tid >> 5, lane = tid & 31, h = tid * 8;
    __shared__ float4 part[2][4];

    float4 hs0 = *(const float4*)(h0 + (size_t)b * Hdim + h);
    float4 hs1 = *(const float4*)(h0 + (size_t)b * Hdim + h + 4);
    float4 dr0 = *(const float4*)(dvec + h);
    float4 dr1 = *(const float4*)(dvec + h + 4);

    float4 Lr[8];   // L[h+i][0..3]
    #pragma unroll
    for (int i = 0; i < 8; i++) Lr[i] = *(const float4*)(L + (size_t)(h + i) * RANKK);
    float4 Ra[4], Rb[4];   // R[r][h..h+3], R[r][h+4..h+7]
    #pragma unroll
    for (int r = 0; r < 4; r++) {
        Ra[r] = *(const float4*)(R + (size_t)r * Hdim + h);
        Rb[r] = *(const float4*)(R + (size_t)r * Hdim + h + 4);
    }

    float* row = out + (size_t)b * TSTEPS * Hdim;
    float4 u0 = *(const float4*)(row + h);
    float4 u1 = *(const float4*)(row + h + 4);

    for (int t = 0; t < TSTEPS; t++) {
        float4 un0 = make_float4(0.f, 0.f, 0.f, 0.f), un1 = un0;
        if (t + 1 < TSTEPS) {
            un0 = *(const float4*)(row + (size_t)(t + 1) * Hdim + h);
            un1 = *(const float4*)(row + (size_t)(t + 1) * Hdim + h + 4);
        }

        float p0 = dot4(Ra[0], hs0) + dot4(Rb[0], hs1);
        float p1 = dot4(Ra[1], hs0) + dot4(Rb[1], hs1);
        float p2 = dot4(Ra[2], hs0) + dot4(Rb[2], hs1);
        float p3 = dot4(Ra[3], hs0) + dot4(Rb[3], hs1);

        #pragma unroll
        for (int off = 16; off >= 1; off >>= 1) {
            p0 += __shfl_xor_sync(0xFFFFFFFFu, p0, off);
            p1 += __shfl_xor_sync(0xFFFFFFFFu, p1, off);
            p2 += __shfl_xor_sync(0xFFFFFFFFu, p2, off);
            p3 += __shfl_xor_sync(0xFFFFFFFFu, p3, off);
        }
        if (lane == 0) part[t & 1][warp] = make_float4(p0, p1, p2, p3);
        __syncthreads();

        float4 pa = part[t & 1][0], pb = part[t & 1][1], pc = part[t & 1][2], pd = part[t & 1][3];
        float v0 = (pa.x + pb.x) + (pc.x + pd.x);
        float v1 = (pa.y + pb.y) + (pc.y + pd.y);
        float v2 = (pa.z + pb.z) + (pc.z + pd.z);
        float v3 = (pa.w + pb.w) + (pc.w + pd.w);
        float4 v = make_float4(v0, v1, v2, v3);

        float a0 = fmaf(dr0.x, hs0.x, u0.x) + dot4(Lr[0], v);
        float a1 = fmaf(dr0.y, hs0.y, u0.y) + dot4(Lr[1], v);
        float a2 = fmaf(dr0.z, hs0.z, u0.z) + dot4(Lr[2], v);
        float a3 = fmaf(dr0.w, hs0.w, u0.w) + dot4(Lr[3], v);
        float a4 = fmaf(dr1.x, hs1.x, u1.x) + dot4(Lr[4], v);
        float a5 = fmaf(dr1.y, hs1.y, u1.y) + dot4(Lr[5], v);
        float a6 = fmaf(dr1.z, hs1.z, u1.z) + dot4(Lr[6], v);
        float a7 = fmaf(dr1.w, hs1.w, u1.w) + dot4(Lr[7], v);

        hs0 = make_float4(tanh_fast(a0), tanh_fast(a1), tanh_fast(a2), tanh_fast(a3));
        hs1 = make_float4(tanh_fast(a4), tanh_fast(a5), tanh_fast(a6), tanh_fast(a7));

        *(float4*)(row + (size_t)t * Hdim + h)     = hs0;
        *(float4*)(row + (size_t)t * Hdim + h + 4) = hs1;
        u0 = un0; u1 = un1;
    }
}

// ======================= launch =======================
extern "C" void kernel_launch(void* const* d_in, const int* in_sizes, int n_in,
                              void* d_out, int out_size) {
    const float* x  = (const float*)d_in[0];
    const float* h0 = (const float*)d_in[1];
    const float* d  = (const float*)d_in[2];
    const float* L  = (const float*)d_in[3];
    const float* R  = (const float*)d_in[4];
    const float* B  = (const float*)d_in[5];
    float* out = (float*)d_out;

    cudaFuncSetAttribute(gemm_mma, cudaFuncAttributeMaxDynamicSharedMemorySize, SMEM_GEMM);

    split_x_kernel<<<(size_t)MTOT * Hdim / 4 / 256, 256>>>(x);
    split_B_kernel<<<(size_t)Hdim * Hdim / 4 / 256, 256>>>(B);
    gemm_mma<<<dim3(Hdim / 256, MTOT / 128), 256, SMEM_GEMM>>>(out);
    recur<<<BATCHN, 128>>>(h0, d, L, R, out);
}

// round 8
// speedup vs baseline: 1.2740x; 1.2740x over previous
#include <cuda_runtime.h>
#include <cuda_bf16.h>
#include <cstdint>
#include <math.h>

#define Hdim   1024
#define RANKK  4
#define BATCHN 128
#define TSTEPS 256
#define MTOT   (BATCHN * TSTEPS)      // 32768

// ======================= helpers =======================
__device__ __forceinline__ uint32_t smem_u32(const void* p) {
    uint32_t a;
    asm("{ .reg .u64 t; cvta.to.shared.u64 t, %1; cvt.u32.u64 %0, t; }" : "=r"(a) : "l"(p));
    return a;
}
__device__ __forceinline__ void cp16(uint32_t dst, const void* src) {
    asm volatile("cp.async.cg.shared.global [%0], [%1], 16;" :: "r"(dst), "l"(src) : "memory");
}
#define CP_COMMIT() asm volatile("cp.async.commit_group;" ::: "memory")

__device__ __forceinline__ void ldsm4(uint32_t* r, uint32_t addr) {
    asm volatile("ldmatrix.sync.aligned.m8n8.x4.shared.b16 {%0,%1,%2,%3}, [%4];"
        : "=r"(r[0]), "=r"(r[1]), "=r"(r[2]), "=r"(r[3]) : "r"(addr));
}
__device__ __forceinline__ void ldsm4t(uint32_t* r, uint32_t addr) {
    asm volatile("ldmatrix.sync.aligned.m8n8.x4.trans.shared.b16 {%0,%1,%2,%3}, [%4];"
        : "=r"(r[0]), "=r"(r[1]), "=r"(r[2]), "=r"(r[3]) : "r"(addr));
}
__device__ __forceinline__ void mma16816(float* c, const uint32_t* a, uint32_t b0, uint32_t b1) {
    asm volatile("mma.sync.aligned.m16n8k16.row.col.f32.bf16.bf16.f32 "
        "{%0,%1,%2,%3}, {%4,%5,%6,%7}, {%8,%9}, {%0,%1,%2,%3};"
        : "+f"(c[0]), "+f"(c[1]), "+f"(c[2]), "+f"(c[3])
        : "r"(a[0]), "r"(a[1]), "r"(a[2]), "r"(a[3]), "r"(b0), "r"(b1));
}

// ======================= bf16 split scratch =======================
__device__ __align__(256) __nv_bfloat16 g_xh[(size_t)MTOT * Hdim];   // 64 MB
__device__ __align__(256) __nv_bfloat16 g_xl[(size_t)MTOT * Hdim];   // 64 MB
__device__ __align__(256) __nv_bfloat16 g_Bh[(size_t)Hdim * Hdim];   // 2 MB  [k][n]
__device__ __align__(256) __nv_bfloat16 g_Bl[(size_t)Hdim * Hdim];

__global__ __launch_bounds__(256) void split_x_kernel(const float* __restrict__ x) {
    size_t i = (size_t)blockIdx.x * 256 + threadIdx.x;
    float4 v = ((const float4*)x)[i];
    union { __nv_bfloat16 b[4]; uint2 u; } Hh, Ll;
    Hh.b[0] = __float2bfloat16(v.x); Ll.b[0] = __float2bfloat16(v.x - __bfloat162float(Hh.b[0]));
    Hh.b[1] = __float2bfloat16(v.y); Ll.b[1] = __float2bfloat16(v.y - __bfloat162float(Hh.b[1]));
    Hh.b[2] = __float2bfloat16(v.z); Ll.b[2] = __float2bfloat16(v.z - __bfloat162float(Hh.b[2]));
    Hh.b[3] = __float2bfloat16(v.w); Ll.b[3] = __float2bfloat16(v.w - __bfloat162float(Hh.b[3]));
    *(uint2*)&g_xh[4 * i] = Hh.u;
    *(uint2*)&g_xl[4 * i] = Ll.u;
}

__global__ __launch_bounds__(256) void split_B_kernel(const float* __restrict__ B) {
    size_t i = (size_t)blockIdx.x * 256 + threadIdx.x;
    float4 v = ((const float4*)B)[i];
    union { __nv_bfloat16 b[4]; uint2 u; } Hh, Ll;
    Hh.b[0] = __float2bfloat16(v.x); Ll.b[0] = __float2bfloat16(v.x - __bfloat162float(Hh.b[0]));
    Hh.b[1] = __float2bfloat16(v.y); Ll.b[1] = __float2bfloat16(v.y - __bfloat162float(Hh.b[1]));
    Hh.b[2] = __float2bfloat16(v.z); Ll.b[2] = __float2bfloat16(v.z - __bfloat162float(Hh.b[2]));
    Hh.b[3] = __float2bfloat16(v.w); Ll.b[3] = __float2bfloat16(v.w - __bfloat162float(Hh.b[3]));
    *(uint2*)&g_Bh[4 * i] = Hh.u;
    *(uint2*)&g_Bl[4 * i] = Ll.u;
}

// ======================= HMMA GEMM (R6 v1, proven 515us) =======================
// C[32768,1024] = xh@Bh + xh@Bl + xl@Bh (virtual K = 3*1024, chunks of 32)
#define BK     32
#define NCHNK  96                    // 3 slabs * 32 chunks
#define ASTRIDE 40                   // halves per A smem row (80 B)
#define BSTRIDE 136                  // halves per B smem row (272 B)
#define ASTG   (128 * ASTRIDE * 2)   // 10240 B per stage
#define BSTG   (BK * BSTRIDE * 2)    // 8704 B per stage
#define NSTAGE 3
#define SMEM_GEMM (NSTAGE * (ASTG + BSTG))   // 56832 B

__device__ __forceinline__ void load_chunk_g(uint32_t sA, uint32_t sB,
                                             const __nv_bfloat16* __restrict__ gA,
                                             const __nv_bfloat16* __restrict__ gB,
                                             int m0, int n0, int k0, int tid) {
    const int arow = tid >> 2, aseg = tid & 3;
    const int brow = tid >> 4, bseg = tid & 15;
    #pragma unroll
    for (int i = 0; i < 2; i++) {
        int ra = arow + i * 64;
        cp16(sA + ra * 80 + aseg * 16, gA + (size_t)(m0 + ra) * Hdim + k0 + aseg * 8);
        int rb = brow + i * 16;
        cp16(sB + rb * 272 + bseg * 16, gB + (size_t)(k0 + rb) * Hdim + n0 + bseg * 8);
    }
}

__global__ __launch_bounds__(256, 2) void gemm_mma(float* __restrict__ C) {
    extern __shared__ char smem[];
    const uint32_t sb  = smem_u32(smem);
    const uint32_t sbB = sb + NSTAGE * ASTG;
    const int tid = threadIdx.x, lane = tid & 31, wid = tid >> 5;
    const int wm = (wid >> 1) * 32;
    const int wn = (wid & 1) * 64;
    const int n0 = blockIdx.x * 128;
    const int m0 = blockIdx.y * 128;

    const __nv_bfloat16* slabA[3] = { g_xh, g_xh, g_xl };
    const __nv_bfloat16* slabB[3] = { g_Bh, g_Bl, g_Bh };

    const int r8 = lane & 7, g = lane >> 3;
    const int mrow = (g & 1) * 8 + r8;
    const int kcolB = (g >> 1) * 16;
    uint32_t offA0 = (uint32_t)(wm + mrow) * 80 + kcolB;
    uint32_t offA1 = (uint32_t)(wm + 16 + mrow) * 80 + kcolB;
    uint32_t offB[4];
    #pragma unroll
    for (int ng = 0; ng < 4; ng++)
        offB[ng] = (uint32_t)mrow * 272 + (uint32_t)(wn + ng * 16) * 2 + kcolB;

    float acc[2][8][4] = {};

    load_chunk_g(sb, sbB, slabA[0], slabB[0], m0, n0, 0, tid);  CP_COMMIT();
    load_chunk_g(sb + ASTG, sbB + BSTG, slabA[0], slabB[0], m0, n0, 32, tid);  CP_COMMIT();

    for (int c = 0; c < NCHNK; c++) {
        const int s = c % NSTAGE;
        asm volatile("cp.async.wait_group 1;" ::: "memory");
        __syncthreads();

        if (c + 2 < NCHNK) {
            const int cn = c + 2, sn = cn % NSTAGE;
            load_chunk_g(sb + sn * ASTG, sbB + sn * BSTG,
                         slabA[cn >> 5], slabB[cn >> 5], m0, n0, (cn & 31) * BK, tid);
        }
        CP_COMMIT();

        const uint32_t aB = sb + s * ASTG;
        const uint32_t bB = sbB + s * BSTG;
        #pragma unroll
        for (int ks = 0; ks < 2; ks++) {
            uint32_t a[2][4];
            ldsm4(a[0], aB + offA0 + ks * 32);
            ldsm4(a[1], aB + offA1 + ks * 32);
            uint32_t b[4][4];
            #pragma unroll
            for (int ng = 0; ng < 4; ng++)
                ldsm4t(b[ng], bB + offB[ng] + ks * 16 * 272);
            #pragma unroll
            for (int mt = 0; mt < 2; mt++)
                #pragma unroll
                for (int nt = 0; nt < 8; nt++)
                    mma16816(acc[mt][nt], a[mt], b[nt >> 1][(nt & 1) * 2], b[nt >> 1][(nt & 1) * 2 + 1]);
        }
    }

    #pragma unroll
    for (int mt = 0; mt < 2; mt++) {
        const int row = m0 + wm + mt * 16 + (lane >> 2);
        #pragma unroll
        for (int nt = 0; nt < 8; nt++) {
            const int col = n0 + wn + nt * 8 + (lane & 3) * 2;
            *(float2*)&C[(size_t)row * Hdim + col]       = make_float2(acc[mt][nt][0], acc[mt][nt][1]);
            *(float2*)&C[(size_t)(row + 8) * Hdim + col] = make_float2(acc[mt][nt][2], acc[mt][nt][3]);
        }
    }
}

// ======================= recurrence: R6 v1 + depth-2 u prefetch =======================
__device__ __forceinline__ float tanh_fast(float x) {
    float ax = fabsf(x);
    float e  = __expf(-2.0f * ax);
    float r  = (1.0f - e) * __frcp_rn(1.0f + e);
    return copysignf(r, x);
}

__global__ __launch_bounds__(256) void recur(const float* __restrict__ h0,
                                             const float* __restrict__ dvec,
                                             const float* __restrict__ L,
                                             const float* __restrict__ R,
                                             float* __restrict__ out) {
    const int b = blockIdx.x, tid = threadIdx.x;
    const int warp = tid >> 5, lane = tid & 31, h = tid * 4;
    __shared__ float4 part[2][8];

    float4 hs = *(const float4*)(h0 + (size_t)b * Hdim + h);
    float4 dr = *(const float4*)(dvec + h);
    float4 L0 = *(const float4*)(L + (size_t)(h + 0) * RANKK);
    float4 L1 = *(const float4*)(L + (size_t)(h + 1) * RANKK);
    float4 L2 = *(const float4*)(L + (size_t)(h + 2) * RANKK);
    float4 L3 = *(const float4*)(L + (size_t)(h + 3) * RANKK);
    float4 R0 = *(const float4*)(R + 0 * Hdim + h);
    float4 R1 = *(const float4*)(R + 1 * Hdim + h);
    float4 R2 = *(const float4*)(R + 2 * Hdim + h);
    float4 R3 = *(const float4*)(R + 3 * Hdim + h);

    float* row = out + (size_t)b * TSTEPS * Hdim;

    // depth-2 prefetch pipeline: at step t we consume u(t), hold u(t+1), issue load u(t+2)
    float4 u  = *(const float4*)(row + h);             // u(0)
    float4 u1 = *(const float4*)(row + Hdim + h);      // u(1)

    for (int t = 0; t < TSTEPS; t++) {
        float4 u2 = make_float4(0.f, 0.f, 0.f, 0.f);
        if (t + 2 < TSTEPS)
            u2 = *(const float4*)(row + (size_t)(t + 2) * Hdim + h);   // issue early; row t+2 untouched until step t+2

        float p0 = R0.x * hs.x + R0.y * hs.y + R0.z * hs.z + R0.w * hs.w;
        float p1 = R1.x * hs.x + R1.y * hs.y + R1.z * hs.z + R1.w * hs.w;
        float p2 = R2.x * hs.x + R2.y * hs.y + R2.z * hs.z + R2.w * hs.w;
        float p3 = R3.x * hs.x + R3.y * hs.y + R3.z * hs.z + R3.w * hs.w;
        #pragma unroll
        for (int off = 16; off >= 1; off >>= 1) {
            p0 += __shfl_xor_sync(0xFFFFFFFFu, p0, off);
            p1 += __shfl_xor_sync(0xFFFFFFFFu, p1, off);
            p2 += __shfl_xor_sync(0xFFFFFFFFu, p2, off);
            p3 += __shfl_xor_sync(0xFFFFFFFFu, p3, off);
        }
        if (lane == 0) part[t & 1][warp] = make_float4(p0, p1, p2, p3);
        __syncthreads();

        float v0 = 0.f, v1 = 0.f, v2 = 0.f, v3 = 0.f;
        #pragma unroll
        for (int w = 0; w < 8; w++) {
            float4 pw = part[t & 1][w];
            v0 += pw.x; v1 += pw.y; v2 += pw.z; v3 += pw.w;
        }
        float a0 = fmaf(dr.x, hs.x, u.x);
        float a1 = fmaf(dr.y, hs.y, u.y);
        float a2 = fmaf(dr.z, hs.z, u.z);
        float a3 = fmaf(dr.w, hs.w, u.w);
        a0 = fmaf(L0.x, v0, fmaf(L0.y, v1, fmaf(L0.z, v2, fmaf(L0.w, v3, a0))));
        a1 = fmaf(L1.x, v0, fmaf(L1.y, v1, fmaf(L1.z, v2, fmaf(L1.w, v3, a1))));
        a2 = fmaf(L2.x, v0, fmaf(L2.y, v1, fmaf(L2.z, v2, fmaf(L2.w, v3, a2))));
        a3 = fmaf(L3.x, v0, fmaf(L3.y, v1, fmaf(L3.z, v2, fmaf(L3.w, v3, a3))));
        hs.x = tanh_fast(a0); hs.y = tanh_fast(a1); hs.z = tanh_fast(a2); hs.w = tanh_fast(a3);
        *(float4*)(row + (size_t)t * Hdim + h) = hs;
        u = u1; u1 = u2;
    }
}

// ======================= launch =======================
extern "C" void kernel_launch(void* const* d_in, const int* in_sizes, int n_in,
                              void* d_out, int out_size) {
    const float* x  = (const float*)d_in[0];
    const float* h0 = (const float*)d_in[1];
    const float* d  = (const float*)d_in[2];
    const float* L  = (const float*)d_in[3];
    const float* R  = (const float*)d_in[4];
    const float* B  = (const float*)d_in[5];
    float* out = (float*)d_out;

    cudaFuncSetAttribute(gemm_mma, cudaFuncAttributeMaxDynamicSharedMemorySize, SMEM_GEMM);

    split_x_kernel<<<(size_t)MTOT * Hdim / 4 / 256, 256>>>(x);
    split_B_kernel<<<(size_t)Hdim * Hdim / 4 / 256, 256>>>(B);
    gemm_mma<<<dim3(Hdim / 128, MTOT / 128), 256, SMEM_GEMM>>>(out);
    recur<<<BATCHN, 256>>>(h0, d, L, R, out);
}

// round 10
// speedup vs baseline: 2.5093x; 1.9697x over previous
#include <cuda_runtime.h>
#include <cuda_fp16.h>
#include <cstdint>
#include <math.h>

#define Hdim   1024
#define RANKK  4
#define BATCHN 128
#define TSTEPS 256
#define MTOT   (BATCHN * TSTEPS)      // 32768

// ======================= helpers =======================
__device__ __forceinline__ uint32_t smem_u32(const void* p) {
    uint32_t a;
    asm("{ .reg .u64 t; cvta.to.shared.u64 t, %1; cvt.u32.u64 %0, t; }" : "=r"(a) : "l"(p));
    return a;
}
__device__ __forceinline__ void cp16(uint32_t dst, const void* src) {
    asm volatile("cp.async.cg.shared.global [%0], [%1], 16;" :: "r"(dst), "l"(src) : "memory");
}
#define CP_COMMIT() asm volatile("cp.async.commit_group;" ::: "memory")

__device__ __forceinline__ void ldsm4(uint32_t* r, uint32_t addr) {
    asm volatile("ldmatrix.sync.aligned.m8n8.x4.shared.b16 {%0,%1,%2,%3}, [%4];"
        : "=r"(r[0]), "=r"(r[1]), "=r"(r[2]), "=r"(r[3]) : "r"(addr));
}
__device__ __forceinline__ void ldsm4t(uint32_t* r, uint32_t addr) {
    asm volatile("ldmatrix.sync.aligned.m8n8.x4.trans.shared.b16 {%0,%1,%2,%3}, [%4];"
        : "=r"(r[0]), "=r"(r[1]), "=r"(r[2]), "=r"(r[3]) : "r"(addr));
}
__device__ __forceinline__ void mma16816(float* c, const uint32_t* a, uint32_t b0, uint32_t b1) {
    asm volatile("mma.sync.aligned.m16n8k16.row.col.f32.f16.f16.f32 "
        "{%0,%1,%2,%3}, {%4,%5,%6,%7}, {%8,%9}, {%0,%1,%2,%3};"
        : "+f"(c[0]), "+f"(c[1]), "+f"(c[2]), "+f"(c[3])
        : "r"(a[0]), "r"(a[1]), "r"(a[2]), "r"(a[3]), "r"(b0), "r"(b1));
}

// ======================= fp16 scratch =======================
__device__ __align__(256) __half g_xf[(size_t)MTOT * Hdim];   // 64 MB
__device__ __align__(256) __half g_Bf[(size_t)Hdim * Hdim];   // 2 MB  [k][n] native layout

__global__ __launch_bounds__(256) void conv_x_kernel(const float* __restrict__ x) {
    size_t i = (size_t)blockIdx.x * 256 + threadIdx.x;
    float4 v = ((const float4*)x)[i];
    union { __half h[4]; uint2 u; } o;
    o.h[0] = __float2half_rn(v.x);
    o.h[1] = __float2half_rn(v.y);
    o.h[2] = __float2half_rn(v.z);
    o.h[3] = __float2half_rn(v.w);
    *(uint2*)&g_xf[4 * i] = o.u;
}

__global__ __launch_bounds__(256) void conv_B_kernel(const float* __restrict__ B) {
    size_t i = (size_t)blockIdx.x * 256 + threadIdx.x;
    float4 v = ((const float4*)B)[i];
    union { __half h[4]; uint2 u; } o;
    o.h[0] = __float2half_rn(v.x);
    o.h[1] = __float2half_rn(v.y);
    o.h[2] = __float2half_rn(v.z);
    o.h[3] = __float2half_rn(v.w);
    *(uint2*)&g_Bf[4 * i] = o.u;
}

// ======================= HMMA GEMM (fp16 single product) =======================
// C[32768,1024] = xf @ Bf, K = 1024, chunks of 32. Tile/pipeline identical to proven R6.
#define BK     32
#define NCHNK  32                    // 1024 / 32
#define ASTRIDE 40                   // halves per A smem row (80 B)
#define BSTRIDE 136                  // halves per B smem row (272 B)
#define ASTG   (128 * ASTRIDE * 2)   // 10240 B per stage
#define BSTG   (BK * BSTRIDE * 2)    // 8704 B per stage
#define NSTAGE 3
#define SMEM_GEMM (NSTAGE * (ASTG + BSTG))   // 56832 B

__device__ __forceinline__ void load_chunk_g(uint32_t sA, uint32_t sB,
                                             int m0, int n0, int k0, int tid) {
    const int arow = tid >> 2, aseg = tid & 3;
    const int brow = tid >> 4, bseg = tid & 15;
    #pragma unroll
    for (int i = 0; i < 2; i++) {
        int ra = arow + i * 64;
        cp16(sA + ra * 80 + aseg * 16, g_xf + (size_t)(m0 + ra) * Hdim + k0 + aseg * 8);
        int rb = brow + i * 16;
        cp16(sB + rb * 272 + bseg * 16, g_Bf + (size_t)(k0 + rb) * Hdim + n0 + bseg * 8);
    }
}

__global__ __launch_bounds__(256, 2) void gemm_mma(float* __restrict__ C) {
    extern __shared__ char smem[];
    const uint32_t sb  = smem_u32(smem);
    const uint32_t sbB = sb + NSTAGE * ASTG;
    const int tid = threadIdx.x, lane = tid & 31, wid = tid >> 5;
    const int wm = (wid >> 1) * 32;
    const int wn = (wid & 1) * 64;
    const int n0 = blockIdx.x * 128;
    const int m0 = blockIdx.y * 128;

    const int r8 = lane & 7, g = lane >> 3;
    const int mrow = (g & 1) * 8 + r8;
    const int kcolB = (g >> 1) * 16;
    uint32_t offA0 = (uint32_t)(wm + mrow) * 80 + kcolB;
    uint32_t offA1 = (uint32_t)(wm + 16 + mrow) * 80 + kcolB;
    uint32_t offB[4];
    #pragma unroll
    for (int ng = 0; ng < 4; ng++)
        offB[ng] = (uint32_t)mrow * 272 + (uint32_t)(wn + ng * 16) * 2 + kcolB;

    float acc[2][8][4] = {};

    load_chunk_g(sb, sbB, m0, n0, 0, tid);  CP_COMMIT();
    load_chunk_g(sb + ASTG, sbB + BSTG, m0, n0, 32, tid);  CP_COMMIT();

    for (int c = 0; c < NCHNK; c++) {
        const int s = c % NSTAGE;
        asm volatile("cp.async.wait_group 1;" ::: "memory");
        __syncthreads();

        if (c + 2 < NCHNK) {
            const int cn = c + 2, sn = cn % NSTAGE;
            load_chunk_g(sb + sn * ASTG, sbB + sn * BSTG, m0, n0, cn * BK, tid);
        }
        CP_COMMIT();

        const uint32_t aB = sb + s * ASTG;
        const uint32_t bB = sbB + s * BSTG;
        #pragma unroll
        for (int ks = 0; ks < 2; ks++) {
            uint32_t a[2][4];
            ldsm4(a[0], aB + offA0 + ks * 32);
            ldsm4(a[1], aB + offA1 + ks * 32);
            uint32_t b[4][4];
            #pragma unroll
            for (int ng = 0; ng < 4; ng++)
                ldsm4t(b[ng], bB + offB[ng] + ks * 16 * 272);
            #pragma unroll
            for (int mt = 0; mt < 2; mt++)
                #pragma unroll
                for (int nt = 0; nt < 8; nt++)
                    mma16816(acc[mt][nt], a[mt], b[nt >> 1][(nt & 1) * 2], b[nt >> 1][(nt & 1) * 2 + 1]);
        }
    }

    #pragma unroll
    for (int mt = 0; mt < 2; mt++) {
        const int row = m0 + wm + mt * 16 + (lane >> 2);
        #pragma unroll
        for (int nt = 0; nt < 8; nt++) {
            const int col = n0 + wn + nt * 8 + (lane & 3) * 2;
            *(float2*)&C[(size_t)row * Hdim + col]       = make_float2(acc[mt][nt][0], acc[mt][nt][1]);
            *(float2*)&C[(size_t)(row + 8) * Hdim + col] = make_float2(acc[mt][nt][2], acc[mt][nt][3]);
        }
    }
}

// ======================= recurrence (exact R6, proven 163.7us) =======================
__device__ __forceinline__ float tanh_fast(float x) {
    float ax = fabsf(x);
    float e  = __expf(-2.0f * ax);
    float r  = (1.0f - e) * __frcp_rn(1.0f + e);
    return copysignf(r, x);
}

__global__ __launch_bounds__(256) void recur(const float* __restrict__ h0,
                                             const float* __restrict__ dvec,
                                             const float* __restrict__ L,
                                             const float* __restrict__ R,
                                             float* __restrict__ out) {
    const int b = blockIdx.x, tid = threadIdx.x;
    const int warp = tid >> 5, lane = tid & 31, h = tid * 4;
    __shared__ float4 part[2][8];

    float4 hs = *(const float4*)(h0 + (size_t)b * Hdim + h);
    float4 dr = *(const float4*)(dvec + h);
    float4 L0 = *(const float4*)(L + (size_t)(h + 0) * RANKK);
    float4 L1 = *(const float4*)(L + (size_t)(h + 1) * RANKK);
    float4 L2 = *(const float4*)(L + (size_t)(h + 2) * RANKK);
    float4 L3 = *(const float4*)(L + (size_t)(h + 3) * RANKK);
    float4 R0 = *(const float4*)(R + 0 * Hdim + h);
    float4 R1 = *(const float4*)(R + 1 * Hdim + h);
    float4 R2 = *(const float4*)(R + 2 * Hdim + h);
    float4 R3 = *(const float4*)(R + 3 * Hdim + h);

    float* row = out + (size_t)b * TSTEPS * Hdim;
    float4 u = *(const float4*)(row + h);
    for (int t = 0; t < TSTEPS; t++) {
        float4 u_next = make_float4(0.f, 0.f, 0.f, 0.f);
        if (t + 1 < TSTEPS) u_next = *(const float4*)(row + (size_t)(t + 1) * Hdim + h);

        float p0 = R0.x * hs.x + R0.y * hs.y + R0.z * hs.z + R0.w * hs.w;
        float p1 = R1.x * hs.x + R1.y * hs.y + R1.z * hs.z + R1.w * hs.w;
        float p2 = R2.x * hs.x + R2.y * hs.y + R2.z * hs.z + R2.w * hs.w;
        float p3 = R3.x * hs.x + R3.y * hs.y + R3.z * hs.z + R3.w * hs.w;
        #pragma unroll
        for (int off = 16; off >= 1; off >>= 1) {
            p0 += __shfl_xor_sync(0xFFFFFFFFu, p0, off);
            p1 += __shfl_xor_sync(0xFFFFFFFFu, p1, off);
            p2 += __shfl_xor_sync(0xFFFFFFFFu, p2, off);
            p3 += __shfl_xor_sync(0xFFFFFFFFu, p3, off);
        }
        if (lane == 0) part[t & 1][warp] = make_float4(p0, p1, p2, p3);
        __syncthreads();

        float v0 = 0.f, v1 = 0.f, v2 = 0.f, v3 = 0.f;
        #pragma unroll
        for (int w = 0; w < 8; w++) {
            float4 pw = part[t & 1][w];
            v0 += pw.x; v1 += pw.y; v2 += pw.z; v3 += pw.w;
        }
        float a0 = fmaf(dr.x, hs.x, u.x);
        float a1 = fmaf(dr.y, hs.y, u.y);
        float a2 = fmaf(dr.z, hs.z, u.z);
        float a3 = fmaf(dr.w, hs.w, u.w);
        a0 = fmaf(L0.x, v0, fmaf(L0.y, v1, fmaf(L0.z, v2, fmaf(L0.w, v3, a0))));
        a1 = fmaf(L1.x, v0, fmaf(L1.y, v1, fmaf(L1.z, v2, fmaf(L1.w, v3, a1))));
        a2 = fmaf(L2.x, v0, fmaf(L2.y, v1, fmaf(L2.z, v2, fmaf(L2.w, v3, a2))));
        a3 = fmaf(L3.x, v0, fmaf(L3.y, v1, fmaf(L3.z, v2, fmaf(L3.w, v3, a3))));
        hs.x = tanh_fast(a0); hs.y = tanh_fast(a1); hs.z = tanh_fast(a2); hs.w = tanh_fast(a3);
        *(float4*)(row + (size_t)t * Hdim + h) = hs;
        u = u_next;
    }
}

// ======================= launch =======================
extern "C" void kernel_launch(void* const* d_in, const int* in_sizes, int n_in,
                              void* d_out, int out_size) {
    const float* x  = (const float*)d_in[0];
    const float* h0 = (const float*)d_in[1];
    const float* d  = (const float*)d_in[2];
    const float* L  = (const float*)d_in[3];
    const float* R  = (const float*)d_in[4];
    const float* B  = (const float*)d_in[5];
    float* out = (float*)d_out;

    cudaFuncSetAttribute(gemm_mma, cudaFuncAttributeMaxDynamicSharedMemorySize, SMEM_GEMM);

    conv_x_kernel<<<(size_t)MTOT * Hdim / 4 / 256, 256>>>(x);
    conv_B_kernel<<<(size_t)Hdim * Hdim / 4 / 256, 256>>>(B);
    gemm_mma<<<dim3(Hdim / 128, MTOT / 128), 256, SMEM_GEMM>>>(out);
    recur<<<BATCHN, 256>>>(h0, d, L, R, out);
}